// round 15
// baseline (speedup 1.0000x reference)
#include <cuda_runtime.h>
#include <math.h>

#define N_NODES   512
#define IN_FEAT   512
#define N_HEADS   8
#define N_HID     64

typedef unsigned long long u64;

// Scratch (device globals: allocation-free rule)
__device__ float d_gtgt[N_HEADS * N_NODES * N_HID];   // [h][n][f]
__device__ float d_attn[N_HEADS * N_NODES * N_NODES]; // [h][i][j]
__device__ float d_u[N_HEADS * N_NODES];              // 0.6 * <w, gsrc[j]>
__device__ float d_v[N_HEADS * N_NODES];              // 0.6 * <w, gtgt[i]>
__device__ u64   d_gspk[N_HEADS * 32 * N_NODES];      // [h][fp][j] packed f-pairs

// ---- packed f32x2 helpers ----
__device__ __forceinline__ u64 pack2(float x, float y) {
    u64 r; asm("mov.b64 %0, {%1,%2};" : "=l"(r) : "f"(x), "f"(y)); return r;
}
__device__ __forceinline__ void unpack2(u64 v, float& x, float& y) {
    asm("mov.b64 {%0,%1}, %2;" : "=f"(x), "=f"(y) : "l"(v));
}
__device__ __forceinline__ u64 add2(u64 a, u64 b) {
    u64 d; asm("add.rn.f32x2 %0, %1, %2;" : "=l"(d) : "l"(a), "l"(b)); return d;
}
__device__ __forceinline__ u64 fma2(u64 a, u64 b, u64 c) {
    u64 d; asm("fma.rn.f32x2 %0, %1, %2, %3;" : "=l"(d) : "l"(a), "l"(b), "l"(c)); return d;
}

// ---------------------------------------------------------------------------
// K1: g = x @ W^T, both weights in ONE launch (grid 16 x 16; y<8 -> source).
// 32n x 64r tile (256 blocks, light regs -> ~2 blocks/SM), 256 thr,
// 2x4 micro-tile, LDS.128 B operand.
// Source half writes d_gspk packed [h][fp][j] + u; target half d_gtgt + v.
// ---------------------------------------------------------------------------
__global__ __launch_bounds__(256) void k1_gemm(const float* __restrict__ x,
                                               const float* __restrict__ Ws,
                                               const float* __restrict__ Wt,
                                               const float* __restrict__ aw) {
    __shared__ float At[16][36];   // [d][n] (32 rows)
    __shared__ float Bt[16][68];   // [d][j] (64 cols)

    const int n0   = blockIdx.x * 32;
    const int mode = (blockIdx.y >= 8);        // 0: source, 1: target
    const int h    = blockIdx.y & 7;
    const int rb   = h * 64;
    const float* W = mode ? Wt : Ws;

    const int t  = threadIdx.x;
    const int tx = t & 15, ty = t >> 4;        // rows 2ty+ii, cols 4tx+q

    u64 acc[2][2] = {};

    for (int k0 = 0; k0 < IN_FEAT; k0 += 16) {
        #pragma unroll
        for (int kk = 0; kk < 2; kk++) {
            const int lin = t + kk * 256;      // 0..511 over 32x16 A elems
            const int d = lin & 15, n = lin >> 4;
            At[d][n] = x[(n0 + n) * IN_FEAT + k0 + d];
        }
        #pragma unroll
        for (int kk = 0; kk < 4; kk++) {
            const int lin = t + kk * 256;      // 0..1023 over 64x16 B elems
            const int d = lin & 15, n = lin >> 4;
            Bt[d][n] = W[(rb + n) * IN_FEAT + k0 + d];
        }
        __syncthreads();
        #pragma unroll
        for (int d2 = 0; d2 < 16; d2++) {
            const float2 a2f = *(const float2*)&At[d2][2 * ty];
            const u64*   bp  = (const u64*)&Bt[d2][4 * tx];
            const u64 b0 = bp[0], b1 = bp[1];
            const u64 a0 = pack2(a2f.x, a2f.x);
            const u64 a1 = pack2(a2f.y, a2f.y);
            acc[0][0] = fma2(a0, b0, acc[0][0]);
            acc[0][1] = fma2(a0, b1, acc[0][1]);
            acc[1][0] = fma2(a1, b0, acc[1][0]);
            acc[1][1] = fma2(a1, b1, acc[1][1]);
        }
        __syncthreads();
    }

    const float w0 = 0.6f * aw[4 * tx],     w1 = 0.6f * aw[4 * tx + 1];
    const float w2 = 0.6f * aw[4 * tx + 2], w3 = 0.6f * aw[4 * tx + 3];
    float* uv = mode ? d_v : d_u;

    #pragma unroll
    for (int ii = 0; ii < 2; ii++) {
        const int n = n0 + 2 * ty + ii;
        float c0, c1, c2, c3;
        unpack2(acc[ii][0], c0, c1);
        unpack2(acc[ii][1], c2, c3);
        if (mode) {
            float* dst = d_gtgt + h * (N_NODES * N_HID) + n * N_HID;
            *(float4*)&dst[4 * tx] = make_float4(c0, c1, c2, c3);
        } else {
            d_gspk[h * 16384 + (2 * tx)     * 512 + n] = pack2(c0, c1);
            d_gspk[h * 16384 + (2 * tx + 1) * 512 + n] = pack2(c2, c3);
        }
        float p = w0 * c0 + w1 * c1 + w2 * c2 + w3 * c3;
        #pragma unroll
        for (int off = 8; off; off >>= 1)
            p += __shfl_down_sync(0xffffffffu, p, off, 16);
        if (tx == 0) uv[h * N_NODES + n] = p;
    }
}

// ---------------------------------------------------------------------------
// K2 (proven R6 512-thread version): A[i,j] = sum_f (0.4 w_f)|gs_jf + gt_if|,
// then score = A + u_j + v_i, mask, softmax over j -> d_attn[h][i][j].
// Also zeroes this block's slice of `out` (for K3's atomics).
// ---------------------------------------------------------------------------
#define K2_SMEM_BYTES (32 * 512 * 8 + (32 * 66 + 64 + 512 + 32) * 4)

__global__ __launch_bounds__(512, 1) void k2_scores(const float* __restrict__ aw,
                                                    const int*   __restrict__ adj,
                                                    float*       __restrict__ out) {
    extern __shared__ char k2sm[];
    u64*   sgs = (u64*)k2sm;                       // [32 fp][512 j]
    float* sgt = (float*)(k2sm + 32 * 512 * 8);    // [32 i][66]
    float* sw  = sgt + 32 * 66;                    // 64 (0.4*w)
    float* su  = sw + 64;                          // 512
    float* sv  = su + 512;                         // 32

    const int h  = blockIdx.y;
    const int i0 = blockIdx.x * 32;
    const int t  = threadIdx.x;

    // zero my slice of out (128 blocks x 2048 floats = full 512x512)
    {
        const int blk = h * 16 + blockIdx.x;
        *(float4*)&out[blk * 2048 + 4 * t] = make_float4(0.f, 0.f, 0.f, 0.f);
    }

    const float* gt_h = d_gtgt + h * (N_NODES * N_HID);

    if (t < 64) sw[t] = 0.4f * aw[t];
    su[t] = d_u[h * N_NODES + t];
    if (t < 32) sv[t] = d_v[h * N_NODES + i0 + t];

    #pragma unroll
    for (int k = 0; k < 4; k++) {
        const int lin = t + k * 512;
        const int i = lin >> 6, f = lin & 63;
        sgt[i * 66 + f] = gt_h[(i0 + i) * N_HID + f];
    }
    {
        const float4* src = (const float4*)(d_gspk + h * 16384);
        float4* dst = (float4*)sgs;
        #pragma unroll
        for (int k = 0; k < 16; k++)
            dst[t + k * 512] = src[t + k * 512];
    }
    __syncthreads();

    const int wid = t >> 5, tj = t & 31;       // warp wid owns rows 2wid, 2wid+1
    const u64 ABS2 = 0x7FFFFFFF7FFFFFFFULL;
    float vals[2][16];

    #pragma unroll
    for (int jt = 0; jt < 4; jt++) {
        u64 acc[2][4] = {};
        #pragma unroll 8
        for (int fp = 0; fp < 32; fp++) {
            const u64 w2 = *(const u64*)&sw[2 * fp];
            const u64 g0 = *(const u64*)&sgt[(2 * wid)     * 66 + 2 * fp];
            const u64 g1 = *(const u64*)&sgt[(2 * wid + 1) * 66 + 2 * fp];
            #pragma unroll
            for (int jj = 0; jj < 4; jj++) {
                const u64 s2 = sgs[fp * 512 + tj + 32 * (4 * jt + jj)];
                const u64 t0 = add2(g0, s2) & ABS2;
                const u64 t1 = add2(g1, s2) & ABS2;
                acc[0][jj] = fma2(t0, w2, acc[0][jj]);
                acc[1][jj] = fma2(t1, w2, acc[1][jj]);
            }
        }
        #pragma unroll
        for (int ii = 0; ii < 2; ii++)
            #pragma unroll
            for (int jj = 0; jj < 4; jj++) {
                float lo, hi; unpack2(acc[ii][jj], lo, hi);
                vals[ii][4 * jt + jj] = lo + hi;
            }
    }

    #pragma unroll
    for (int ii = 0; ii < 2; ii++) {
        const int i  = 2 * wid + ii;
        const int gi = i0 + i;
        const float svi = sv[i];
        const int* arow = adj + gi * N_NODES;

        float mx = -INFINITY;
        #pragma unroll
        for (int m = 0; m < 16; m++) {
            const int j = tj + 32 * m;
            float v = vals[ii][m] + su[j] + svi;
            v = arow[j] ? v : -INFINITY;
            vals[ii][m] = v;
            mx = fmaxf(mx, v);
        }
        #pragma unroll
        for (int o = 16; o; o >>= 1) mx = fmaxf(mx, __shfl_xor_sync(0xffffffffu, mx, o));

        float s = 0.f;
        #pragma unroll
        for (int m = 0; m < 16; m++) {
            const float e = __expf(vals[ii][m] - mx);
            vals[ii][m] = e;
            s += e;
        }
        #pragma unroll
        for (int o = 16; o; o >>= 1) s += __shfl_xor_sync(0xffffffffu, s, o);
        const float inv = 1.f / s;

        float* dst = d_attn + h * (N_NODES * N_NODES) + gi * N_NODES;
        #pragma unroll
        for (int m = 0; m < 16; m++)
            dst[tj + 32 * m] = vals[ii][m] * inv;
    }
}

// ---------------------------------------------------------------------------
// K3: out[i, h*64+f] += sum_{j in chunk} attn[h][i][j] * g_tgt[h][j][f]
// 8-way j-split (blockIdx.z) -> 1024 blocks, ~4 blocks/SM. atomicAdd epilogue
// (out zeroed by K2). Row-pair f32x2 packing; A = broadcast LDS.128/warp/j.
// ---------------------------------------------------------------------------
__global__ __launch_bounds__(256) void k3_out(float* __restrict__ out) {
    __shared__ u64   sa2[32][18];   // [j][i-pair], padded
    __shared__ float sb[32][68];    // [j][f]

    const int i0  = blockIdx.x * 32;
    const int h   = blockIdx.y;
    const int jc0 = blockIdx.z * 64;
    const int t   = threadIdx.x;
    const int w   = t >> 5, l = t & 31;  // warp w: rows 4w..4w+3; lane l: f 2l,2l+1

    const float* attn_h = d_attn + h * (N_NODES * N_NODES);
    const float* gt_h   = d_gtgt + h * (N_NODES * N_HID);

    const int ip = t >> 4;    // 0..15 i-pair (rows 2ip, 2ip+1)
    const int j2 = t & 15;    // 0..15 j-pair group

    u64 acc[2][2] = {};       // [row-pair rp][ff]

    #pragma unroll
    for (int jc = 0; jc < 2; jc++) {
        const int j0 = jc0 + jc * 32;
        {
            const float2 r0 = *(const float2*)&attn_h[(i0 + 2 * ip)     * N_NODES + j0 + 2 * j2];
            const float2 r1 = *(const float2*)&attn_h[(i0 + 2 * ip + 1) * N_NODES + j0 + 2 * j2];
            sa2[2 * j2][ip]     = pack2(r0.x, r1.x);
            sa2[2 * j2 + 1][ip] = pack2(r0.y, r1.y);
        }
        #pragma unroll
        for (int k = 0; k < 8; k++) {
            const int lin = t + k * 256;
            const int j = lin >> 6, f = lin & 63;
            sb[j][f] = gt_h[(j0 + j) * N_HID + f];
        }
        __syncthreads();
        #pragma unroll
        for (int j = 0; j < 32; j++) {
            const u64* ap = &sa2[j][2 * w];       // LDS.128 broadcast
            const u64 a0 = ap[0], a1 = ap[1];
            const float2 bf = *(const float2*)&sb[j][2 * l];
            const u64 b0 = pack2(bf.x, bf.x);
            const u64 b1 = pack2(bf.y, bf.y);
            acc[0][0] = fma2(a0, b0, acc[0][0]);
            acc[0][1] = fma2(a0, b1, acc[0][1]);
            acc[1][0] = fma2(a1, b0, acc[1][0]);
            acc[1][1] = fma2(a1, b1, acc[1][1]);
        }
        __syncthreads();
    }

    #pragma unroll
    for (int rp = 0; rp < 2; rp++)
        #pragma unroll
        for (int ff = 0; ff < 2; ff++) {
            float o0, o1; unpack2(acc[rp][ff], o0, o1);
            const int i = i0 + 4 * w + 2 * rp;
            atomicAdd(&out[i       * 512 + h * N_HID + 2 * l + ff], o0);
            atomicAdd(&out[(i + 1) * 512 + h * N_HID + 2 * l + ff], o1);
        }
}

// ---------------------------------------------------------------------------
// K4: d_attn[h][i][j] -> attention [i][j][h]. Smem-staged, 2 rows per block,
// float4 both sides, 512 threads. (Depends only on K2.)
// ---------------------------------------------------------------------------
__global__ __launch_bounds__(512) void k4_transpose(float* __restrict__ att_out) {
    __shared__ float s[2][8][516];
    const int i0 = blockIdx.x * 2;
    const int t  = threadIdx.x;

    #pragma unroll
    for (int k = 0; k < 4; k++) {
        const int lin = t + k * 512;               // 0..2047 float4 slots
        const int i2 = lin >> 10, hh = (lin >> 7) & 7, j4 = lin & 127;
        const float4 v = *(const float4*)&d_attn[hh * (N_NODES * N_NODES) +
                                                 (i0 + i2) * N_NODES + 4 * j4];
        *(float4*)&s[i2][hh][4 * j4] = v;
    }
    __syncthreads();

    #pragma unroll
    for (int k = 0; k < 4; k++) {
        const int lin = t + k * 512;
        const int i2 = lin >> 10, r = lin & 1023;
        const int j = r >> 1, h0 = (r & 1) * 4;
        const float4 v = make_float4(s[i2][h0 + 0][j], s[i2][h0 + 1][j],
                                     s[i2][h0 + 2][j], s[i2][h0 + 3][j]);
        *(float4*)&att_out[(i0 + i2) * (N_NODES * N_HEADS) + j * N_HEADS + h0] = v;
    }
}

// ---------------------------------------------------------------------------
extern "C" void kernel_launch(void* const* d_in, const int* in_sizes, int n_in,
                              void* d_out, int out_size) {
    const float* x   = (const float*)d_in[0];  // h [1,512,512]
    const float* Ws  = (const float*)d_in[1];  // W_source [512,512]
    const float* Wt  = (const float*)d_in[2];  // W_target [512,512]
    const float* aw  = (const float*)d_in[3];  // attn_w [64]
    const int*   adj = (const int*)d_in[4];    // adjacency [512,512,1]

    float* out = (float*)d_out;
    float* att_out =
        (out_size >= N_NODES * N_HEADS * N_HID + N_NODES * N_NODES * N_HEADS)
            ? out + N_NODES * N_HEADS * N_HID : (float*)0;

    cudaFuncSetAttribute(k2_scores, cudaFuncAttributeMaxDynamicSharedMemorySize,
                         K2_SMEM_BYTES);

    k1_gemm<<<dim3(16, 16), 256>>>(x, Ws, Wt, aw);                // launch 1
    k2_scores<<<dim3(16, 8), 512, K2_SMEM_BYTES>>>(aw, adj, out); // launch 2
    if (att_out) {
        k4_transpose<<<256, 512>>>(att_out);                       // launch 3
    }
    k3_out<<<dim3(16, 8, 8), 256>>>(out);                          // launch 4 -> idx5
}

// round 16
// speedup vs baseline: 1.3427x; 1.3427x over previous
#include <cuda_runtime.h>
#include <math.h>

#define N_NODES   512
#define IN_FEAT   512
#define N_HEADS   8
#define N_HID     64

typedef unsigned long long u64;

// Scratch (device globals: allocation-free rule)
__device__ float d_gtgt[N_HEADS * N_NODES * N_HID];   // [h][n][f]
__device__ float d_attn[N_HEADS * N_NODES * N_NODES]; // [h][i][j]
__device__ float d_u[N_HEADS * N_NODES];              // 0.6 * <w, gsrc[j]>
__device__ float d_v[N_HEADS * N_NODES];              // 0.6 * <w, gtgt[i]>
__device__ u64   d_gspk[N_HEADS * 32 * N_NODES];      // [h][fp][j] packed f-pairs

// ---- packed f32x2 helpers ----
__device__ __forceinline__ u64 pack2(float x, float y) {
    u64 r; asm("mov.b64 %0, {%1,%2};" : "=l"(r) : "f"(x), "f"(y)); return r;
}
__device__ __forceinline__ void unpack2(u64 v, float& x, float& y) {
    asm("mov.b64 {%0,%1}, %2;" : "=f"(x), "=f"(y) : "l"(v));
}
__device__ __forceinline__ u64 add2(u64 a, u64 b) {
    u64 d; asm("add.rn.f32x2 %0, %1, %2;" : "=l"(d) : "l"(a), "l"(b)); return d;
}
__device__ __forceinline__ u64 fma2(u64 a, u64 b, u64 c) {
    u64 d; asm("fma.rn.f32x2 %0, %1, %2, %3;" : "=l"(d) : "l"(a), "l"(b), "l"(c)); return d;
}

// ---------------------------------------------------------------------------
// K1 (R11 proven config): g = x @ W^T, both weights in ONE launch
// (grid 8 x 16; y<8 -> source). 64n x 64r tile, 256 thr, 4x4 micro-tile,
// LDS.128 operands. Source half writes d_gspk packed [h][fp][j] + u;
// target half writes d_gtgt [h][n][f] + v.
// ---------------------------------------------------------------------------
__global__ __launch_bounds__(256) void k1_gemm(const float* __restrict__ x,
                                               const float* __restrict__ Ws,
                                               const float* __restrict__ Wt,
                                               const float* __restrict__ aw) {
    __shared__ float At[16][68];   // [d][n]
    __shared__ float Bt[16][68];   // [d][j]

    const int n0   = blockIdx.x * 64;
    const int mode = (blockIdx.y >= 8);        // 0: source, 1: target
    const int h    = blockIdx.y & 7;
    const int rb   = h * 64;
    const float* W = mode ? Wt : Ws;

    const int t  = threadIdx.x;
    const int tx = t & 15, ty = t >> 4;        // rows 4ty+ii, cols 4tx+q

    u64 acc[4][2] = {};

    for (int k0 = 0; k0 < IN_FEAT; k0 += 16) {
        #pragma unroll
        for (int kk = 0; kk < 4; kk++) {
            const int lin = t + kk * 256;
            const int d = lin & 15, n = lin >> 4;
            At[d][n] = x[(n0 + n) * IN_FEAT + k0 + d];
            Bt[d][n] = W[(rb + n) * IN_FEAT + k0 + d];
        }
        __syncthreads();
        #pragma unroll
        for (int d2 = 0; d2 < 16; d2++) {
            const float4 a4 = *(const float4*)&At[d2][4 * ty];
            const u64*   bp = (const u64*)&Bt[d2][4 * tx];
            const u64 b0 = bp[0], b1 = bp[1];
            const float av[4] = {a4.x, a4.y, a4.z, a4.w};
            #pragma unroll
            for (int ii = 0; ii < 4; ii++) {
                const u64 a2 = pack2(av[ii], av[ii]);
                acc[ii][0] = fma2(a2, b0, acc[ii][0]);
                acc[ii][1] = fma2(a2, b1, acc[ii][1]);
            }
        }
        __syncthreads();
    }

    const float w0 = 0.6f * aw[4 * tx],     w1 = 0.6f * aw[4 * tx + 1];
    const float w2 = 0.6f * aw[4 * tx + 2], w3 = 0.6f * aw[4 * tx + 3];
    float* uv = mode ? d_v : d_u;

    #pragma unroll
    for (int ii = 0; ii < 4; ii++) {
        const int n = n0 + 4 * ty + ii;
        float c0, c1, c2, c3;
        unpack2(acc[ii][0], c0, c1);
        unpack2(acc[ii][1], c2, c3);
        if (mode) {
            float* dst = d_gtgt + h * (N_NODES * N_HID) + n * N_HID;
            *(float4*)&dst[4 * tx] = make_float4(c0, c1, c2, c3);
        } else {
            d_gspk[h * 16384 + (2 * tx)     * 512 + n] = pack2(c0, c1);
            d_gspk[h * 16384 + (2 * tx + 1) * 512 + n] = pack2(c2, c3);
        }
        float p = w0 * c0 + w1 * c1 + w2 * c2 + w3 * c3;
        #pragma unroll
        for (int off = 8; off; off >>= 1)
            p += __shfl_down_sync(0xffffffffu, p, off, 16);
        if (tx == 0) uv[h * N_NODES + n] = p;
    }
}

// ---------------------------------------------------------------------------
// K2 (proven R6 512-thread version): A[i,j] = sum_f (0.4 w_f)|gs_jf + gt_if|,
// then score = A + u_j + v_i, mask, softmax over j -> d_attn[h][i][j].
// Also zeroes this block's slice of `out` (for K3's atomics).
// ---------------------------------------------------------------------------
#define K2_SMEM_BYTES (32 * 512 * 8 + (32 * 66 + 64 + 512 + 32) * 4)

__global__ __launch_bounds__(512, 1) void k2_scores(const float* __restrict__ aw,
                                                    const int*   __restrict__ adj,
                                                    float*       __restrict__ out) {
    extern __shared__ char k2sm[];
    u64*   sgs = (u64*)k2sm;                       // [32 fp][512 j]
    float* sgt = (float*)(k2sm + 32 * 512 * 8);    // [32 i][66]
    float* sw  = sgt + 32 * 66;                    // 64 (0.4*w)
    float* su  = sw + 64;                          // 512
    float* sv  = su + 512;                         // 32

    const int h  = blockIdx.y;
    const int i0 = blockIdx.x * 32;
    const int t  = threadIdx.x;

    // zero my slice of out (128 blocks x 2048 floats = full 512x512)
    {
        const int blk = h * 16 + blockIdx.x;
        *(float4*)&out[blk * 2048 + 4 * t] = make_float4(0.f, 0.f, 0.f, 0.f);
    }

    const float* gt_h = d_gtgt + h * (N_NODES * N_HID);

    if (t < 64) sw[t] = 0.4f * aw[t];
    su[t] = d_u[h * N_NODES + t];
    if (t < 32) sv[t] = d_v[h * N_NODES + i0 + t];

    #pragma unroll
    for (int k = 0; k < 4; k++) {
        const int lin = t + k * 512;
        const int i = lin >> 6, f = lin & 63;
        sgt[i * 66 + f] = gt_h[(i0 + i) * N_HID + f];
    }
    {
        const float4* src = (const float4*)(d_gspk + h * 16384);
        float4* dst = (float4*)sgs;
        #pragma unroll
        for (int k = 0; k < 16; k++)
            dst[t + k * 512] = src[t + k * 512];
    }
    __syncthreads();

    const int wid = t >> 5, tj = t & 31;       // warp wid owns rows 2wid, 2wid+1
    const u64 ABS2 = 0x7FFFFFFF7FFFFFFFULL;
    float vals[2][16];

    #pragma unroll
    for (int jt = 0; jt < 4; jt++) {
        u64 acc[2][4] = {};
        #pragma unroll 8
        for (int fp = 0; fp < 32; fp++) {
            const u64 w2 = *(const u64*)&sw[2 * fp];
            const u64 g0 = *(const u64*)&sgt[(2 * wid)     * 66 + 2 * fp];
            const u64 g1 = *(const u64*)&sgt[(2 * wid + 1) * 66 + 2 * fp];
            #pragma unroll
            for (int jj = 0; jj < 4; jj++) {
                const u64 s2 = sgs[fp * 512 + tj + 32 * (4 * jt + jj)];
                const u64 t0 = add2(g0, s2) & ABS2;
                const u64 t1 = add2(g1, s2) & ABS2;
                acc[0][jj] = fma2(t0, w2, acc[0][jj]);
                acc[1][jj] = fma2(t1, w2, acc[1][jj]);
            }
        }
        #pragma unroll
        for (int ii = 0; ii < 2; ii++)
            #pragma unroll
            for (int jj = 0; jj < 4; jj++) {
                float lo, hi; unpack2(acc[ii][jj], lo, hi);
                vals[ii][4 * jt + jj] = lo + hi;
            }
    }

    #pragma unroll
    for (int ii = 0; ii < 2; ii++) {
        const int i  = 2 * wid + ii;
        const int gi = i0 + i;
        const float svi = sv[i];
        const int* arow = adj + gi * N_NODES;

        float mx = -INFINITY;
        #pragma unroll
        for (int m = 0; m < 16; m++) {
            const int j = tj + 32 * m;
            float v = vals[ii][m] + su[j] + svi;
            v = arow[j] ? v : -INFINITY;
            vals[ii][m] = v;
            mx = fmaxf(mx, v);
        }
        #pragma unroll
        for (int o = 16; o; o >>= 1) mx = fmaxf(mx, __shfl_xor_sync(0xffffffffu, mx, o));

        float s = 0.f;
        #pragma unroll
        for (int m = 0; m < 16; m++) {
            const float e = __expf(vals[ii][m] - mx);
            vals[ii][m] = e;
            s += e;
        }
        #pragma unroll
        for (int o = 16; o; o >>= 1) s += __shfl_xor_sync(0xffffffffu, s, o);
        const float inv = 1.f / s;

        float* dst = d_attn + h * (N_NODES * N_NODES) + gi * N_NODES;
        #pragma unroll
        for (int m = 0; m < 16; m++)
            dst[tj + 32 * m] = vals[ii][m] * inv;
    }
}

// ---------------------------------------------------------------------------
// K3 (R15 proven config): out[i, h*64+f] += sum_{j in 64-chunk} attn * g_tgt
// 8-way j-split (blockIdx.z) -> 1024 blocks. atomicAdd epilogue (out zeroed
// by K2). Row-pair f32x2 packing; A = broadcast LDS.128 per warp per j.
// ---------------------------------------------------------------------------
__global__ __launch_bounds__(256) void k3_out(float* __restrict__ out) {
    __shared__ u64   sa2[32][18];   // [j][i-pair], padded
    __shared__ float sb[32][68];    // [j][f]

    const int i0  = blockIdx.x * 32;
    const int h   = blockIdx.y;
    const int jc0 = blockIdx.z * 64;
    const int t   = threadIdx.x;
    const int w   = t >> 5, l = t & 31;  // warp w: rows 4w..4w+3; lane l: f 2l,2l+1

    const float* attn_h = d_attn + h * (N_NODES * N_NODES);
    const float* gt_h   = d_gtgt + h * (N_NODES * N_HID);

    const int ip = t >> 4;    // 0..15 i-pair (rows 2ip, 2ip+1)
    const int j2 = t & 15;    // 0..15 j-pair group

    u64 acc[2][2] = {};       // [row-pair rp][ff]

    #pragma unroll
    for (int jc = 0; jc < 2; jc++) {
        const int j0 = jc0 + jc * 32;
        {
            const float2 r0 = *(const float2*)&attn_h[(i0 + 2 * ip)     * N_NODES + j0 + 2 * j2];
            const float2 r1 = *(const float2*)&attn_h[(i0 + 2 * ip + 1) * N_NODES + j0 + 2 * j2];
            sa2[2 * j2][ip]     = pack2(r0.x, r1.x);
            sa2[2 * j2 + 1][ip] = pack2(r0.y, r1.y);
        }
        #pragma unroll
        for (int k = 0; k < 8; k++) {
            const int lin = t + k * 256;
            const int j = lin >> 6, f = lin & 63;
            sb[j][f] = gt_h[(j0 + j) * N_HID + f];
        }
        __syncthreads();
        #pragma unroll
        for (int j = 0; j < 32; j++) {
            const u64* ap = &sa2[j][2 * w];       // LDS.128 broadcast
            const u64 a0 = ap[0], a1 = ap[1];
            const float2 bf = *(const float2*)&sb[j][2 * l];
            const u64 b0 = pack2(bf.x, bf.x);
            const u64 b1 = pack2(bf.y, bf.y);
            acc[0][0] = fma2(a0, b0, acc[0][0]);
            acc[0][1] = fma2(a0, b1, acc[0][1]);
            acc[1][0] = fma2(a1, b0, acc[1][0]);
            acc[1][1] = fma2(a1, b1, acc[1][1]);
        }
        __syncthreads();
    }

    #pragma unroll
    for (int rp = 0; rp < 2; rp++)
        #pragma unroll
        for (int ff = 0; ff < 2; ff++) {
            float o0, o1; unpack2(acc[rp][ff], o0, o1);
            const int i = i0 + 4 * w + 2 * rp;
            atomicAdd(&out[i       * 512 + h * N_HID + 2 * l + ff], o0);
            atomicAdd(&out[(i + 1) * 512 + h * N_HID + 2 * l + ff], o1);
        }
}

// ---------------------------------------------------------------------------
// K4: d_attn[h][i][j] -> attention [i][j][h]. Smem-staged, 2 rows per block,
// float4 both sides, 512 threads. (Depends only on K2.)
// ---------------------------------------------------------------------------
__global__ __launch_bounds__(512) void k4_transpose(float* __restrict__ att_out) {
    __shared__ float s[2][8][516];
    const int i0 = blockIdx.x * 2;
    const int t  = threadIdx.x;

    #pragma unroll
    for (int k = 0; k < 4; k++) {
        const int lin = t + k * 512;               // 0..2047 float4 slots
        const int i2 = lin >> 10, hh = (lin >> 7) & 7, j4 = lin & 127;
        const float4 v = *(const float4*)&d_attn[hh * (N_NODES * N_NODES) +
                                                 (i0 + i2) * N_NODES + 4 * j4];
        *(float4*)&s[i2][hh][4 * j4] = v;
    }
    __syncthreads();

    #pragma unroll
    for (int k = 0; k < 4; k++) {
        const int lin = t + k * 512;
        const int i2 = lin >> 10, r = lin & 1023;
        const int j = r >> 1, h0 = (r & 1) * 4;
        const float4 v = make_float4(s[i2][h0 + 0][j], s[i2][h0 + 1][j],
                                     s[i2][h0 + 2][j], s[i2][h0 + 3][j]);
        *(float4*)&att_out[(i0 + i2) * (N_NODES * N_HEADS) + j * N_HEADS + h0] = v;
    }
}

// ---------------------------------------------------------------------------
extern "C" void kernel_launch(void* const* d_in, const int* in_sizes, int n_in,
                              void* d_out, int out_size) {
    const float* x   = (const float*)d_in[0];  // h [1,512,512]
    const float* Ws  = (const float*)d_in[1];  // W_source [512,512]
    const float* Wt  = (const float*)d_in[2];  // W_target [512,512]
    const float* aw  = (const float*)d_in[3];  // attn_w [64]
    const int*   adj = (const int*)d_in[4];    // adjacency [512,512,1]

    float* out = (float*)d_out;
    float* att_out =
        (out_size >= N_NODES * N_HEADS * N_HID + N_NODES * N_NODES * N_HEADS)
            ? out + N_NODES * N_HEADS * N_HID : (float*)0;

    cudaFuncSetAttribute(k2_scores, cudaFuncAttributeMaxDynamicSharedMemorySize,
                         K2_SMEM_BYTES);

    k1_gemm<<<dim3(8, 16), 256>>>(x, Ws, Wt, aw);                 // launch 1
    k2_scores<<<dim3(16, 8), 512, K2_SMEM_BYTES>>>(aw, adj, out); // launch 2
    if (att_out) {
        k4_transpose<<<256, 512>>>(att_out);                       // launch 3
    }
    k3_out<<<dim3(16, 8, 8), 256>>>(out);                          // launch 4 -> idx5
}